// round 16
// baseline (speedup 1.0000x reference)
#include <cuda_runtime.h>
#include <cuda_fp16.h>
#include <cstdint>

#define D_MODEL 1024
#define N_HEADS 16
#define D_K     64
#define BATCH   2
#define SEQ     2048
#define M_ROWS  (BATCH * SEQ)   // 4096

// Scratch (allocation-free rule: __device__ globals).
__device__ uint32_t t_q [M_ROWS * D_MODEL / 2];   // fp16 natural acts [m][512 u32]
__device__ uint32_t t_k [M_ROWS * D_MODEL / 2];
__device__ uint32_t t_v [M_ROWS * D_MODEL / 2];
__device__ uint32_t t_wq[D_MODEL * D_MODEL / 2];  // fp16 TRANSPOSED weights Wt[n][512 u32]
__device__ uint32_t t_wk[D_MODEL * D_MODEL / 2];
__device__ uint32_t t_wv[D_MODEL * D_MODEL / 2];
__device__ uint32_t t_wo[D_MODEL * D_MODEL / 2];
__device__ uint32_t g_Q [M_ROWS * D_MODEL / 2];   // fp16 natural, pre-scaled
__device__ uint32_t g_K [M_ROWS * D_MODEL / 2];   // fp16 natural
__device__ uint32_t g_V [M_ROWS * D_MODEL / 2];   // fp16 V^T: [(b*16+h)*64+d][2048 halves]
__device__ uint32_t g_O [M_ROWS * D_MODEL / 2];   // fp16 natural (attn out)

__device__ __forceinline__ uint32_t pack_h2(float lo, float hi) {
    __half2 h = __floats2half2_rn(lo, hi);
    return *(uint32_t*)&h;
}

__device__ __forceinline__ void mma_f16(float c[4],
                                        uint32_t a0, uint32_t a1, uint32_t a2, uint32_t a3,
                                        uint32_t b0, uint32_t b1) {
    asm volatile(
        "mma.sync.aligned.m16n8k16.row.col.f32.f16.f16.f32 "
        "{%0,%1,%2,%3}, {%4,%5,%6,%7}, {%8,%9}, {%0,%1,%2,%3};"
        : "+f"(c[0]), "+f"(c[1]), "+f"(c[2]), "+f"(c[3])
        : "r"(a0), "r"(a1), "r"(a2), "r"(a3), "r"(b0), "r"(b1));
}

__device__ __forceinline__ void ldsm_x4(uint32_t& r0, uint32_t& r1,
                                        uint32_t& r2, uint32_t& r3, uint32_t addr) {
    asm volatile("ldmatrix.sync.aligned.m8n8.x4.shared.b16 {%0,%1,%2,%3}, [%4];"
                 : "=r"(r0), "=r"(r1), "=r"(r2), "=r"(r3) : "r"(addr));
}

__device__ __forceinline__ uint32_t smem_u32(const void* p) {
    return (uint32_t)__cvta_generic_to_shared(p);
}
__device__ __forceinline__ void cpasync16(uint32_t dst, const void* src) {
    asm volatile("cp.async.cg.shared.global [%0], [%1], 16;" :: "r"(dst), "l"(src));
}
__device__ __forceinline__ void cpasync_commit() {
    asm volatile("cp.async.commit_group;");
}
template<int N> __device__ __forceinline__ void cpasync_wait() {
    asm volatile("cp.async.wait_group %0;" :: "n"(N));
}

// ldmatrix per-lane offsets (u32 units) for pitch P
__device__ __forceinline__ int ldsm_a_off(int lane, int P) {
    return ((lane & 7) + ((lane >> 3) & 1) * 8) * P + (lane >> 4) * 4;
}
__device__ __forceinline__ int ldsm_b_off(int lane, int P) {
    return (lane & 7) * P + ((lane >> 3) & 1) * 4 + (lane >> 4) * 8 * P;
}

// ---------------------------------------------------------------------------
// Pre-pass 1: fp32 -> fp16 natural acts (fused q/k/v).
// ---------------------------------------------------------------------------
__global__ __launch_bounds__(256)
void cvt3_kernel(const float4* __restrict__ q, const float4* __restrict__ k,
                 const float4* __restrict__ v,
                 uint2* __restrict__ tq, uint2* __restrict__ tk,
                 uint2* __restrict__ tv, int n4)
{
    int i = blockIdx.x * 256 + threadIdx.x;
    if (i >= n4) return;
    const float4* in = (blockIdx.y == 0) ? q : (blockIdx.y == 1) ? k : v;
    uint2*       out = (blockIdx.y == 0) ? tq : (blockIdx.y == 1) ? tk : tv;
    float4 a = in[i];
    uint2 u = { pack_h2(a.x, a.y), pack_h2(a.z, a.w) };
    out[i] = u;
}

// ---------------------------------------------------------------------------
// Pre-pass 2: transpose + cvt all 4 weights: W[k][n] fp32 -> Wt[n][k] fp16.
// ---------------------------------------------------------------------------
__global__ __launch_bounds__(256)
void wT4_kernel(const float* __restrict__ wq, const float* __restrict__ wk,
                const float* __restrict__ wv, const float* __restrict__ wo,
                __half* __restrict__ twq, __half* __restrict__ twk,
                __half* __restrict__ twv, __half* __restrict__ two)
{
    __shared__ float ts[32][33];
    const float* W  = (blockIdx.z == 0) ? wq  : (blockIdx.z == 1) ? wk  :
                      (blockIdx.z == 2) ? wv  : wo;
    __half*      Wt = (blockIdx.z == 0) ? twq : (blockIdx.z == 1) ? twk :
                      (blockIdx.z == 2) ? twv : two;
    int k0 = blockIdx.x * 32, n0 = blockIdx.y * 32;
    int tx = threadIdx.x, ty = threadIdx.y;
    #pragma unroll
    for (int r = 0; r < 4; r++)
        ts[ty + r * 8][tx] = W[(size_t)(k0 + ty + r * 8) * 1024 + n0 + tx];
    __syncthreads();
    #pragma unroll
    for (int r = 0; r < 4; r++) {
        int n = ty + r * 8;
        Wt[(size_t)(n0 + n) * 1024 + k0 + tx] = __float2half_rn(ts[tx][n]);
    }
}

// ---------------------------------------------------------------------------
// GEMM core body (shared by fused-QKV and final kernels). Round-14 form.
// ---------------------------------------------------------------------------
#define GP 36
#define GST (128 * GP)
#define GEMM_SMEM ((4 * GST) * 4)     // 73728 B

struct GemmAcc { float c[4][4][4]; };

__device__ __forceinline__ void gemm_mainloop(
    const uint32_t* __restrict__ A, const uint32_t* __restrict__ Wt,
    uint32_t* sg, int m0, int n0, int tid, int lane, int wid, GemmAcc& acc)
{
    uint32_t* Asm = sg;
    uint32_t* Bsm = sg + 2 * GST;
    const int warp_m = wid & 1;
    const int warp_n = wid >> 1;
    const int aoff = ldsm_a_off(lane, GP);
    const int boff = ldsm_b_off(lane, GP);

    #pragma unroll
    for (int mt = 0; mt < 4; mt++)
        #pragma unroll
        for (int nt = 0; nt < 4; nt++)
            #pragma unroll
            for (int i = 0; i < 4; i++) acc.c[mt][nt][i] = 0.f;

    #pragma unroll
    for (int i = 0; i < 4; i++) {
        int idx = tid + i * 256;
        int row = idx >> 3, ch = (idx & 7) * 4;
        cpasync16(smem_u32(&Asm[row * GP + ch]), &A [(size_t)(m0 + row) * 512 + ch]);
        cpasync16(smem_u32(&Bsm[row * GP + ch]), &Wt[(size_t)(n0 + row) * 512 + ch]);
    }
    cpasync_commit();

    int st = 0;
    for (int k0 = 0; k0 < 512; k0 += 32) {
        cpasync_wait<0>();
        __syncthreads();

        if (k0 + 32 < 512) {
            uint32_t* Ad = Asm + (st ^ 1) * GST;
            uint32_t* Bd = Bsm + (st ^ 1) * GST;
            #pragma unroll
            for (int i = 0; i < 4; i++) {
                int idx = tid + i * 256;
                int row = idx >> 3, ch = (idx & 7) * 4;
                cpasync16(smem_u32(&Ad[row * GP + ch]),
                          &A [(size_t)(m0 + row) * 512 + k0 + 32 + ch]);
                cpasync16(smem_u32(&Bd[row * GP + ch]),
                          &Wt[(size_t)(n0 + row) * 512 + k0 + 32 + ch]);
            }
            cpasync_commit();
        }

        const uint32_t* As = Asm + st * GST;
        const uint32_t* Bs = Bsm + st * GST;

        uint32_t af[2][4][4], bf[2][4][2];
        #pragma unroll
        for (int mt = 0; mt < 4; mt++)
            ldsm_x4(af[0][mt][0], af[0][mt][1], af[0][mt][2], af[0][mt][3],
                    smem_u32(&As[(warp_m * 64 + mt * 16) * GP + aoff]));
        #pragma unroll
        for (int ntp = 0; ntp < 2; ntp++)
            ldsm_x4(bf[0][ntp * 2][0], bf[0][ntp * 2][1],
                    bf[0][ntp * 2 + 1][0], bf[0][ntp * 2 + 1][1],
                    smem_u32(&Bs[(warp_n * 32 + ntp * 16) * GP + boff]));

        #pragma unroll
        for (int ks = 0; ks < 4; ks++) {
            int cur = ks & 1, nxt = cur ^ 1;
            if (ks < 3) {
                #pragma unroll
                for (int mt = 0; mt < 4; mt++)
                    ldsm_x4(af[nxt][mt][0], af[nxt][mt][1], af[nxt][mt][2], af[nxt][mt][3],
                            smem_u32(&As[(warp_m * 64 + mt * 16) * GP + (ks + 1) * 8 + aoff]));
                #pragma unroll
                for (int ntp = 0; ntp < 2; ntp++)
                    ldsm_x4(bf[nxt][ntp * 2][0], bf[nxt][ntp * 2][1],
                            bf[nxt][ntp * 2 + 1][0], bf[nxt][ntp * 2 + 1][1],
                            smem_u32(&Bs[(warp_n * 32 + ntp * 16) * GP + (ks + 1) * 8 + boff]));
            }
            #pragma unroll
            for (int mt = 0; mt < 4; mt++)
                #pragma unroll
                for (int nt = 0; nt < 4; nt++)
                    mma_f16(acc.c[mt][nt],
                            af[cur][mt][0], af[cur][mt][1], af[cur][mt][2], af[cur][mt][3],
                            bf[cur][nt][0], bf[cur][nt][1]);
        }
        st ^= 1;
    }
}

// Fused QKV projection: blockIdx.z selects {A, W, bias, C, alpha, epilogue}.
__global__ __launch_bounds__(256)
void gemm_qkv(const float* __restrict__ b_q, const float* __restrict__ b_k,
              const float* __restrict__ b_v)
{
    extern __shared__ uint32_t sg[];
    const int tid  = threadIdx.x;
    const int lane = tid & 31;
    const int wid  = tid >> 5;
    const int gid  = lane >> 2;
    const int tg   = lane & 3;
    const int m0 = blockIdx.y * 128;
    const int n0 = blockIdx.x * 128;
    const int z  = blockIdx.z;

    const uint32_t* A  = (z == 0) ? t_q  : (z == 1) ? t_k  : t_v;
    const uint32_t* Wt = (z == 0) ? t_wq : (z == 1) ? t_wk : t_wv;
    const float*  bias = (z == 0) ? b_q  : (z == 1) ? b_k  : b_v;
    const float  alpha = (z == 0) ? 0.125f : 1.0f;

    GemmAcc acc;
    gemm_mainloop(A, Wt, sg, m0, n0, tid, lane, wid, acc);

    const int warp_m = wid & 1;
    const int warp_n = wid >> 1;
    #pragma unroll
    for (int mt = 0; mt < 4; mt++) {
        int r0 = m0 + warp_m * 64 + mt * 16 + gid;
        #pragma unroll
        for (int nt = 0; nt < 4; nt++) {
            int col = n0 + warp_n * 32 + nt * 8 + tg * 2;
            float2 bb = *(const float2*)&bias[col];
            float v00 = alpha * (acc.c[mt][nt][0] + bb.x);
            float v01 = alpha * (acc.c[mt][nt][1] + bb.y);
            float v10 = alpha * (acc.c[mt][nt][2] + bb.x);
            float v11 = alpha * (acc.c[mt][nt][3] + bb.y);
            if (z < 2) {
                uint32_t* C = (z == 0) ? g_Q : g_K;
                C[(size_t)r0 * 512 + (col >> 1)]       = pack_h2(v00, v01);
                C[(size_t)(r0 + 8) * 512 + (col >> 1)] = pack_h2(v10, v11);
            } else {
                __half* VT = (__half*)g_V;
                int bi = r0 >> 11, tok = r0 & 2047;
                int h = col >> 6, d = col & 63;
                size_t row0 = ((size_t)(bi * 16 + h) * 64 + d) * 2048;
                size_t row1 = row0 + 2048;
                VT[row0 + tok]     = __float2half_rn(v00);
                VT[row1 + tok]     = __float2half_rn(v01);
                VT[row0 + tok + 8] = __float2half_rn(v10);
                VT[row1 + tok + 8] = __float2half_rn(v11);
            }
        }
    }
}

// Final output projection: fp32 natural out.
__global__ __launch_bounds__(256)
void gemm_out(const float* __restrict__ bias, float* __restrict__ Cout)
{
    extern __shared__ uint32_t sg[];
    const int tid  = threadIdx.x;
    const int lane = tid & 31;
    const int wid  = tid >> 5;
    const int gid  = lane >> 2;
    const int tg   = lane & 3;
    const int m0 = blockIdx.y * 128;
    const int n0 = blockIdx.x * 128;

    GemmAcc acc;
    gemm_mainloop(g_O, t_wo, sg, m0, n0, tid, lane, wid, acc);

    const int warp_m = wid & 1;
    const int warp_n = wid >> 1;
    #pragma unroll
    for (int mt = 0; mt < 4; mt++) {
        int r0 = m0 + warp_m * 64 + mt * 16 + gid;
        #pragma unroll
        for (int nt = 0; nt < 4; nt++) {
            int col = n0 + warp_n * 32 + nt * 8 + tg * 2;
            float2 bb = *(const float2*)&bias[col];
            *(float2*)&Cout[(size_t)r0 * D_MODEL + col] =
                make_float2(acc.c[mt][nt][0] + bb.x, acc.c[mt][nt][1] + bb.y);
            *(float2*)&Cout[(size_t)(r0 + 8) * D_MODEL + col] =
                make_float2(acc.c[mt][nt][2] + bb.x, acc.c[mt][nt][3] + bb.y);
        }
    }
}

// ---------------------------------------------------------------------------
// FP16 flash attention. P stays in REGISTERS: the S-accumulator layout equals
// the m16n8k16 A-fragment layout, so PV fragments are pack_h2 of s[] directly
// (no Ps smem, no syncwarps, no P ldmatrix). smem = 36864 B.
// ---------------------------------------------------------------------------
#define AKP 36
#define AK_ST (64 * AKP)
#define AV_ST (64 * AKP)
#define ATTN_SMEM ((2 * AK_ST + 2 * AV_ST) * 4)

__global__ __launch_bounds__(256)
void attn_f16(const uint32_t* __restrict__ Q,
              const uint32_t* __restrict__ K,
              const uint32_t* __restrict__ V,
              uint32_t* __restrict__ O)
{
    extern __shared__ uint32_t sa[];
    uint32_t* Kbuf = sa;
    uint32_t* Vbuf = sa + 2 * AK_ST;

    const int tid  = threadIdx.x;
    const int lane = tid & 31;
    const int wid  = tid >> 5;
    const int gid  = lane >> 2;
    const int tg   = lane & 3;
    const int rb   = wid * 16;

    const int q0 = blockIdx.x * 128;
    const int h  = blockIdx.y;
    const int b  = blockIdx.z;

    const int boff = ldsm_b_off(lane, AKP);

    const uint32_t* Qb  = Q + (size_t)b * SEQ * 512 + h * 32;
    const uint32_t* Kb  = K + (size_t)b * SEQ * 512 + h * 32;
    const uint32_t* Vtb = V + ((size_t)(b * 16 + h) * 64) * 1024;

    uint32_t qf[4][4];
    {
        const uint32_t* qr0 = Qb + (size_t)(q0 + rb + gid) * 512;
        const uint32_t* qr1 = qr0 + (size_t)8 * 512;
        #pragma unroll
        for (int ks = 0; ks < 4; ks++) {
            qf[ks][0] = qr0[ks * 8 + tg    ];
            qf[ks][1] = qr1[ks * 8 + tg    ];
            qf[ks][2] = qr0[ks * 8 + tg + 4];
            qf[ks][3] = qr1[ks * 8 + tg + 4];
        }
    }

    #pragma unroll
    for (int i = 0; i < 2; i++) {
        int idx = tid + i * 256;
        int r = idx >> 3, ch = (idx & 7) * 4;
        cpasync16(smem_u32(&Kbuf[r * AKP + ch]), &Kb[(size_t)r * 512 + ch]);
        cpasync16(smem_u32(&Vbuf[r * AKP + ch]), &Vtb[(size_t)r * 1024 + ch]);
    }
    cpasync_commit();

    float o[8][4];
    #pragma unroll
    for (int nt = 0; nt < 8; nt++)
        #pragma unroll
        for (int i = 0; i < 4; i++) o[nt][i] = 0.f;
    float m_i[2] = { -1e30f, -1e30f };
    float l_i[2] = { 0.f, 0.f };

    int st = 0;
    for (int kt = 0; kt < SEQ; kt += 64) {
        cpasync_wait<0>();
        __syncthreads();

        if (kt + 64 < SEQ) {
            uint32_t* Kd = Kbuf + (st ^ 1) * AK_ST;
            uint32_t* Vd = Vbuf + (st ^ 1) * AV_ST;
            #pragma unroll
            for (int i = 0; i < 2; i++) {
                int idx = tid + i * 256;
                int r = idx >> 3, ch = (idx & 7) * 4;
                cpasync16(smem_u32(&Kd[r * AKP + ch]),
                          &Kb[(size_t)(kt + 64 + r) * 512 + ch]);
                cpasync16(smem_u32(&Vd[r * AKP + ch]),
                          &Vtb[(size_t)r * 1024 + (kt + 64) / 2 + ch]);
            }
            cpasync_commit();
        }

        const uint32_t* Ks = Kbuf + st * AK_ST;
        const uint32_t* Vs = Vbuf + st * AV_ST;

        // S = Q @ K^T
        float s[8][4];
        #pragma unroll
        for (int nt = 0; nt < 8; nt++)
            #pragma unroll
            for (int i = 0; i < 4; i++) s[nt][i] = 0.f;

        #pragma unroll
        for (int ks = 0; ks < 4; ks++) {
            uint32_t kf[8][2];
            #pragma unroll
            for (int ntp = 0; ntp < 4; ntp++) {
                int base = (ntp * 16) * AKP + ks * 8 + boff;
                ldsm_x4(kf[ntp * 2][0], kf[ntp * 2][1],
                        kf[ntp * 2 + 1][0], kf[ntp * 2 + 1][1],
                        smem_u32(&Ks[base]));
            }
            #pragma unroll
            for (int nt = 0; nt < 8; nt++)
                mma_f16(s[nt], qf[ks][0], qf[ks][1], qf[ks][2], qf[ks][3],
                        kf[nt][0], kf[nt][1]);
        }

        // Online softmax
        #pragma unroll
        for (int half = 0; half < 2; half++) {
            float mx = -1e30f;
            #pragma unroll
            for (int nt = 0; nt < 8; nt++)
                mx = fmaxf(mx, fmaxf(s[nt][half * 2], s[nt][half * 2 + 1]));
            mx = fmaxf(mx, __shfl_xor_sync(0xffffffffu, mx, 1));
            mx = fmaxf(mx, __shfl_xor_sync(0xffffffffu, mx, 2));

            float mnew = fmaxf(m_i[half], mx);
            float corr = __expf(m_i[half] - mnew);
            float rs = 0.f;
            #pragma unroll
            for (int nt = 0; nt < 8; nt++) {
                s[nt][half * 2]     = __expf(s[nt][half * 2]     - mnew);
                s[nt][half * 2 + 1] = __expf(s[nt][half * 2 + 1] - mnew);
                rs += s[nt][half * 2] + s[nt][half * 2 + 1];
            }
            rs += __shfl_xor_sync(0xffffffffu, rs, 1);
            rs += __shfl_xor_sync(0xffffffffu, rs, 2);

            l_i[half] = l_i[half] * corr + rs;
            m_i[half] = mnew;
            #pragma unroll
            for (int nt = 0; nt < 8; nt++) {
                o[nt][half * 2]     *= corr;
                o[nt][half * 2 + 1] *= corr;
            }
        }

        // O += P @ V : P fragments built directly from s[] registers.
        // a0=(row gid, keys 16ks+2tg,+1)=s[2ks][0,1]; a1=(row gid+8)=s[2ks][2,3];
        // a2=(row gid, keys +8)=s[2ks+1][0,1]; a3=s[2ks+1][2,3].
        #pragma unroll
        for (int ks = 0; ks < 4; ks++) {
            uint32_t pf0 = pack_h2(s[2 * ks    ][0], s[2 * ks    ][1]);
            uint32_t pf1 = pack_h2(s[2 * ks    ][2], s[2 * ks    ][3]);
            uint32_t pf2 = pack_h2(s[2 * ks + 1][0], s[2 * ks + 1][1]);
            uint32_t pf3 = pack_h2(s[2 * ks + 1][2], s[2 * ks + 1][3]);
            uint32_t vf[8][2];
            #pragma unroll
            for (int ntp = 0; ntp < 4; ntp++) {
                int base = (ntp * 16) * AKP + ks * 8 + boff;
                ldsm_x4(vf[ntp * 2][0], vf[ntp * 2][1],
                        vf[ntp * 2 + 1][0], vf[ntp * 2 + 1][1],
                        smem_u32(&Vs[base]));
            }
            #pragma unroll
            for (int nt = 0; nt < 8; nt++)
                mma_f16(o[nt], pf0, pf1, pf2, pf3, vf[nt][0], vf[nt][1]);
        }
        st ^= 1;
    }

    float inv0 = 1.0f / l_i[0];
    float inv1 = 1.0f / l_i[1];
    uint32_t* Ob = O + (size_t)b * SEQ * 512 + h * 32;
    int r0 = q0 + rb + gid;
    #pragma unroll
    for (int nt = 0; nt < 8; nt++) {
        int u = nt * 4 + tg;
        Ob[(size_t)r0 * 512 + u]       = pack_h2(o[nt][0] * inv0, o[nt][1] * inv0);
        Ob[(size_t)(r0 + 8) * 512 + u] = pack_h2(o[nt][2] * inv1, o[nt][3] * inv1);
    }
}

// ---------------------------------------------------------------------------
// kernel_launch — inputs: q, k, v, w_q, b_q, w_k, b_k, w_v, b_v, w_o, b_o
// ---------------------------------------------------------------------------
extern "C" void kernel_launch(void* const* d_in, const int* in_sizes, int n_in,
                              void* d_out, int out_size)
{
    const float* q   = (const float*)d_in[0];
    const float* k   = (const float*)d_in[1];
    const float* v   = (const float*)d_in[2];
    const float* w_q = (const float*)d_in[3];
    const float* b_q = (const float*)d_in[4];
    const float* w_k = (const float*)d_in[5];
    const float* b_k = (const float*)d_in[6];
    const float* w_v = (const float*)d_in[7];
    const float* b_v = (const float*)d_in[8];
    const float* w_o = (const float*)d_in[9];
    const float* b_o = (const float*)d_in[10];
    float* out = (float*)d_out;

    uint32_t *tq, *tk, *tv, *twq, *twk, *twv, *two, *gq, *gk, *gv, *go;
    cudaGetSymbolAddress((void**)&tq,  t_q);
    cudaGetSymbolAddress((void**)&tk,  t_k);
    cudaGetSymbolAddress((void**)&tv,  t_v);
    cudaGetSymbolAddress((void**)&twq, t_wq);
    cudaGetSymbolAddress((void**)&twk, t_wk);
    cudaGetSymbolAddress((void**)&twv, t_wv);
    cudaGetSymbolAddress((void**)&two, t_wo);
    cudaGetSymbolAddress((void**)&gq,  g_Q);
    cudaGetSymbolAddress((void**)&gk,  g_K);
    cudaGetSymbolAddress((void**)&gv,  g_V);
    cudaGetSymbolAddress((void**)&go,  g_O);

    cudaFuncSetAttribute(gemm_qkv, cudaFuncAttributeMaxDynamicSharedMemorySize, GEMM_SMEM);
    cudaFuncSetAttribute(gemm_out, cudaFuncAttributeMaxDynamicSharedMemorySize, GEMM_SMEM);
    cudaFuncSetAttribute(attn_f16, cudaFuncAttributeMaxDynamicSharedMemorySize, ATTN_SMEM);

    const int n4_act = M_ROWS * D_MODEL / 4;
    dim3 act_grid(n4_act / 256, 3);
    cvt3_kernel<<<act_grid, 256>>>((const float4*)q, (const float4*)k, (const float4*)v,
                                   (uint2*)tq, (uint2*)tk, (uint2*)tv, n4_act);
    dim3 wt_grid(32, 32, 4), wt_block(32, 8);
    wT4_kernel<<<wt_grid, wt_block>>>(w_q, w_k, w_v, w_o,
                                      (__half*)twq, (__half*)twk, (__half*)twv, (__half*)two);

    dim3 qkv_grid(D_MODEL / 128, M_ROWS / 128, 3);   // (8, 32, 3) = 768 CTAs
    gemm_qkv<<<qkv_grid, 256, GEMM_SMEM>>>(b_q, b_k, b_v);

    dim3 attn_grid(SEQ / 128, N_HEADS, BATCH);       // (16, 16, 2)
    attn_f16<<<attn_grid, 256, ATTN_SMEM>>>(gq, gk, gv, go);

    dim3 out_grid(D_MODEL / 128, M_ROWS / 128);      // (8, 32)
    gemm_out<<<out_grid, 256, GEMM_SMEM>>>(b_o, out);
}

// round 17
// speedup vs baseline: 1.4583x; 1.4583x over previous
#include <cuda_runtime.h>
#include <cuda_fp16.h>
#include <cstdint>

#define D_MODEL 1024
#define N_HEADS 16
#define D_K     64
#define BATCH   2
#define SEQ     2048
#define M_ROWS  (BATCH * SEQ)   // 4096

// Scratch (allocation-free rule: __device__ globals).
__device__ uint32_t t_q [M_ROWS * D_MODEL / 2];   // fp16 natural acts [m][512 u32]
__device__ uint32_t t_k [M_ROWS * D_MODEL / 2];
__device__ uint32_t t_v [M_ROWS * D_MODEL / 2];
__device__ uint32_t t_wq[D_MODEL * D_MODEL / 2];  // fp16 TRANSPOSED weights Wt[n][512 u32]
__device__ uint32_t t_wk[D_MODEL * D_MODEL / 2];
__device__ uint32_t t_wv[D_MODEL * D_MODEL / 2];
__device__ uint32_t t_wo[D_MODEL * D_MODEL / 2];
__device__ uint32_t g_Q [M_ROWS * D_MODEL / 2];   // fp16 natural, pre-scaled
__device__ uint32_t g_K [M_ROWS * D_MODEL / 2];   // fp16 natural
__device__ uint32_t g_V [M_ROWS * D_MODEL / 2];   // fp16 V^T: [(b*16+h)*64+d][2048 halves]
__device__ uint32_t g_O [M_ROWS * D_MODEL / 2];   // fp16 natural (attn out)

__device__ __forceinline__ uint32_t pack_h2(float lo, float hi) {
    __half2 h = __floats2half2_rn(lo, hi);
    return *(uint32_t*)&h;
}

__device__ __forceinline__ void mma_f16(float c[4],
                                        uint32_t a0, uint32_t a1, uint32_t a2, uint32_t a3,
                                        uint32_t b0, uint32_t b1) {
    asm volatile(
        "mma.sync.aligned.m16n8k16.row.col.f32.f16.f16.f32 "
        "{%0,%1,%2,%3}, {%4,%5,%6,%7}, {%8,%9}, {%0,%1,%2,%3};"
        : "+f"(c[0]), "+f"(c[1]), "+f"(c[2]), "+f"(c[3])
        : "r"(a0), "r"(a1), "r"(a2), "r"(a3), "r"(b0), "r"(b1));
}

__device__ __forceinline__ void ldsm_x4(uint32_t& r0, uint32_t& r1,
                                        uint32_t& r2, uint32_t& r3, uint32_t addr) {
    asm volatile("ldmatrix.sync.aligned.m8n8.x4.shared.b16 {%0,%1,%2,%3}, [%4];"
                 : "=r"(r0), "=r"(r1), "=r"(r2), "=r"(r3) : "r"(addr));
}

__device__ __forceinline__ uint32_t smem_u32(const void* p) {
    return (uint32_t)__cvta_generic_to_shared(p);
}
__device__ __forceinline__ void cpasync16(uint32_t dst, const void* src) {
    asm volatile("cp.async.cg.shared.global [%0], [%1], 16;" :: "r"(dst), "l"(src));
}
__device__ __forceinline__ void cpasync_commit() {
    asm volatile("cp.async.commit_group;");
}
template<int N> __device__ __forceinline__ void cpasync_wait() {
    asm volatile("cp.async.wait_group %0;" :: "n"(N));
}

// ldmatrix per-lane offsets (u32 units) for pitch P
__device__ __forceinline__ int ldsm_a_off(int lane, int P) {
    return ((lane & 7) + ((lane >> 3) & 1) * 8) * P + (lane >> 4) * 4;
}
__device__ __forceinline__ int ldsm_b_off(int lane, int P) {
    return (lane & 7) * P + ((lane >> 3) & 1) * 4 + (lane >> 4) * 8 * P;
}

// ---------------------------------------------------------------------------
// Fused pre-pass: z=0..2 -> act cvt (q/k/v fp32->fp16 natural);
//                 z=3..6 -> weight transpose+cvt (W[k][n] -> Wt[n][k] fp16).
// grid (4096, 1, 7), 256 threads. Weight blocks use x < 1024.
// ---------------------------------------------------------------------------
__global__ __launch_bounds__(256)
void prep_kernel(const float4* __restrict__ q, const float4* __restrict__ k,
                 const float4* __restrict__ v,
                 uint2* __restrict__ tq, uint2* __restrict__ tk, uint2* __restrict__ tv,
                 const float* __restrict__ wq, const float* __restrict__ wk,
                 const float* __restrict__ wv, const float* __restrict__ wo,
                 __half* __restrict__ twq, __half* __restrict__ twk,
                 __half* __restrict__ twv, __half* __restrict__ two,
                 int n4_act)
{
    const int z = blockIdx.z;
    const int tid = threadIdx.x;
    if (z < 3) {
        int i = blockIdx.x * 256 + tid;
        if (i >= n4_act) return;
        const float4* in = (z == 0) ? q : (z == 1) ? k : v;
        uint2*       out = (z == 0) ? tq : (z == 1) ? tk : tv;
        float4 a = in[i];
        uint2 u = { pack_h2(a.x, a.y), pack_h2(a.z, a.w) };
        out[i] = u;
    } else {
        if (blockIdx.x >= 1024) return;
        __shared__ float ts[32][33];
        const int zz = z - 3;
        const float* W  = (zz == 0) ? wq  : (zz == 1) ? wk  : (zz == 2) ? wv  : wo;
        __half*      Wt = (zz == 0) ? twq : (zz == 1) ? twk : (zz == 2) ? twv : two;
        int k0 = (blockIdx.x & 31) * 32, n0 = (blockIdx.x >> 5) * 32;
        int tx = tid & 31, ty = tid >> 5;
        #pragma unroll
        for (int r = 0; r < 4; r++)
            ts[ty + r * 8][tx] = W[(size_t)(k0 + ty + r * 8) * 1024 + n0 + tx];
        __syncthreads();
        #pragma unroll
        for (int r = 0; r < 4; r++) {
            int n = ty + r * 8;
            Wt[(size_t)(n0 + n) * 1024 + k0 + tx] = __float2half_rn(ts[tx][n]);
        }
    }
}

// ---------------------------------------------------------------------------
// GEMM core: 3-stage cp.async ring, ldmatrix + frag-pipelined mma.
// A fp16 natural [m][512u32]; Wt fp16 transposed [n][512u32].
// BM=BN=128, BK=64 halves, 256 thr, warp 64x32, pitch 36.
// ---------------------------------------------------------------------------
#define GP 36
#define GST (128 * GP)
#define GEMM_SMEM (6 * GST * 4)       // 3 stages x (A+B) = 110592 B

struct GemmAcc { float c[4][4][4]; };

__device__ __forceinline__ void gemm_load_tile(
    const uint32_t* __restrict__ A, const uint32_t* __restrict__ Wt,
    uint32_t* Asm, uint32_t* Bsm, int m0, int n0, int tid, int kt, int s)
{
    uint32_t* Ad = Asm + s * GST;
    uint32_t* Bd = Bsm + s * GST;
    #pragma unroll
    for (int i = 0; i < 4; i++) {
        int idx = tid + i * 256;
        int row = idx >> 3, ch = (idx & 7) * 4;
        cpasync16(smem_u32(&Ad[row * GP + ch]), &A [(size_t)(m0 + row) * 512 + kt * 32 + ch]);
        cpasync16(smem_u32(&Bd[row * GP + ch]), &Wt[(size_t)(n0 + row) * 512 + kt * 32 + ch]);
    }
}

__device__ __forceinline__ void gemm_mainloop(
    const uint32_t* __restrict__ A, const uint32_t* __restrict__ Wt,
    uint32_t* sg, int m0, int n0, int tid, int lane, int wid, GemmAcc& acc)
{
    uint32_t* Asm = sg;
    uint32_t* Bsm = sg + 3 * GST;
    const int warp_m = wid & 1;
    const int warp_n = wid >> 1;
    const int aoff = ldsm_a_off(lane, GP);
    const int boff = ldsm_b_off(lane, GP);

    #pragma unroll
    for (int mt = 0; mt < 4; mt++)
        #pragma unroll
        for (int nt = 0; nt < 4; nt++)
            #pragma unroll
            for (int i = 0; i < 4; i++) acc.c[mt][nt][i] = 0.f;

    // Prologue: tiles 0, 1 into stages 0, 1 (one group each)
    gemm_load_tile(A, Wt, Asm, Bsm, m0, n0, tid, 0, 0); cpasync_commit();
    gemm_load_tile(A, Wt, Asm, Bsm, m0, n0, tid, 1, 1); cpasync_commit();

    int s_cur = 0;   // stage holding tile it
    int s_pf  = 2;   // stage for tile it+2
    for (int it = 0; it < 16; it++) {
        cpasync_wait<1>();            // tile it's group drained (1 still in flight)
        __syncthreads();              // also frees stage s_pf (read 2 iters ago)

        if (it + 2 < 16)
            gemm_load_tile(A, Wt, Asm, Bsm, m0, n0, tid, it + 2, s_pf);
        cpasync_commit();             // always commit (empty groups keep count exact)

        const uint32_t* As = Asm + s_cur * GST;
        const uint32_t* Bs = Bsm + s_cur * GST;

        uint32_t af[2][4][4], bf[2][4][2];
        #pragma unroll
        for (int mt = 0; mt < 4; mt++)
            ldsm_x4(af[0][mt][0], af[0][mt][1], af[0][mt][2], af[0][mt][3],
                    smem_u32(&As[(warp_m * 64 + mt * 16) * GP + aoff]));
        #pragma unroll
        for (int ntp = 0; ntp < 2; ntp++)
            ldsm_x4(bf[0][ntp * 2][0], bf[0][ntp * 2][1],
                    bf[0][ntp * 2 + 1][0], bf[0][ntp * 2 + 1][1],
                    smem_u32(&Bs[(warp_n * 32 + ntp * 16) * GP + boff]));

        #pragma unroll
        for (int ks = 0; ks < 4; ks++) {
            int cur = ks & 1, nxt = cur ^ 1;
            if (ks < 3) {
                #pragma unroll
                for (int mt = 0; mt < 4; mt++)
                    ldsm_x4(af[nxt][mt][0], af[nxt][mt][1], af[nxt][mt][2], af[nxt][mt][3],
                            smem_u32(&As[(warp_m * 64 + mt * 16) * GP + (ks + 1) * 8 + aoff]));
                #pragma unroll
                for (int ntp = 0; ntp < 2; ntp++)
                    ldsm_x4(bf[nxt][ntp * 2][0], bf[nxt][ntp * 2][1],
                            bf[nxt][ntp * 2 + 1][0], bf[nxt][ntp * 2 + 1][1],
                            smem_u32(&Bs[(warp_n * 32 + ntp * 16) * GP + (ks + 1) * 8 + boff]));
            }
            #pragma unroll
            for (int mt = 0; mt < 4; mt++)
                #pragma unroll
                for (int nt = 0; nt < 4; nt++)
                    mma_f16(acc.c[mt][nt],
                            af[cur][mt][0], af[cur][mt][1], af[cur][mt][2], af[cur][mt][3],
                            bf[cur][nt][0], bf[cur][nt][1]);
        }
        s_cur = (s_cur == 2) ? 0 : s_cur + 1;
        s_pf  = (s_pf  == 2) ? 0 : s_pf  + 1;
    }
}

// Fused QKV projection: blockIdx.z selects {A, W, bias, C, alpha, epilogue}.
__global__ __launch_bounds__(256)
void gemm_qkv(const float* __restrict__ b_q, const float* __restrict__ b_k,
              const float* __restrict__ b_v)
{
    extern __shared__ uint32_t sg[];
    const int tid  = threadIdx.x;
    const int lane = tid & 31;
    const int wid  = tid >> 5;
    const int gid  = lane >> 2;
    const int tg   = lane & 3;
    const int m0 = blockIdx.y * 128;
    const int n0 = blockIdx.x * 128;
    const int z  = blockIdx.z;

    const uint32_t* A  = (z == 0) ? t_q  : (z == 1) ? t_k  : t_v;
    const uint32_t* Wt = (z == 0) ? t_wq : (z == 1) ? t_wk : t_wv;
    const float*  bias = (z == 0) ? b_q  : (z == 1) ? b_k  : b_v;
    const float  alpha = (z == 0) ? 0.125f : 1.0f;

    GemmAcc acc;
    gemm_mainloop(A, Wt, sg, m0, n0, tid, lane, wid, acc);

    const int warp_m = wid & 1;
    const int warp_n = wid >> 1;
    #pragma unroll
    for (int mt = 0; mt < 4; mt++) {
        int r0 = m0 + warp_m * 64 + mt * 16 + gid;
        #pragma unroll
        for (int nt = 0; nt < 4; nt++) {
            int col = n0 + warp_n * 32 + nt * 8 + tg * 2;
            float2 bb = *(const float2*)&bias[col];
            float v00 = alpha * (acc.c[mt][nt][0] + bb.x);
            float v01 = alpha * (acc.c[mt][nt][1] + bb.y);
            float v10 = alpha * (acc.c[mt][nt][2] + bb.x);
            float v11 = alpha * (acc.c[mt][nt][3] + bb.y);
            if (z < 2) {
                uint32_t* C = (z == 0) ? g_Q : g_K;
                C[(size_t)r0 * 512 + (col >> 1)]       = pack_h2(v00, v01);
                C[(size_t)(r0 + 8) * 512 + (col >> 1)] = pack_h2(v10, v11);
            } else {
                __half* VT = (__half*)g_V;
                int bi = r0 >> 11, tok = r0 & 2047;
                int h = col >> 6, d = col & 63;
                size_t row0 = ((size_t)(bi * 16 + h) * 64 + d) * 2048;
                size_t row1 = row0 + 2048;
                VT[row0 + tok]     = __float2half_rn(v00);
                VT[row1 + tok]     = __float2half_rn(v01);
                VT[row0 + tok + 8] = __float2half_rn(v10);
                VT[row1 + tok + 8] = __float2half_rn(v11);
            }
        }
    }
}

// Final output projection: fp32 natural out.
__global__ __launch_bounds__(256)
void gemm_out(const float* __restrict__ bias, float* __restrict__ Cout)
{
    extern __shared__ uint32_t sg[];
    const int tid  = threadIdx.x;
    const int lane = tid & 31;
    const int wid  = tid >> 5;
    const int gid  = lane >> 2;
    const int tg   = lane & 3;
    const int m0 = blockIdx.y * 128;
    const int n0 = blockIdx.x * 128;

    GemmAcc acc;
    gemm_mainloop(g_O, t_wo, sg, m0, n0, tid, lane, wid, acc);

    const int warp_m = wid & 1;
    const int warp_n = wid >> 1;
    #pragma unroll
    for (int mt = 0; mt < 4; mt++) {
        int r0 = m0 + warp_m * 64 + mt * 16 + gid;
        #pragma unroll
        for (int nt = 0; nt < 4; nt++) {
            int col = n0 + warp_n * 32 + nt * 8 + tg * 2;
            float2 bb = *(const float2*)&bias[col];
            *(float2*)&Cout[(size_t)r0 * D_MODEL + col] =
                make_float2(acc.c[mt][nt][0] + bb.x, acc.c[mt][nt][1] + bb.y);
            *(float2*)&Cout[(size_t)(r0 + 8) * D_MODEL + col] =
                make_float2(acc.c[mt][nt][2] + bb.x, acc.c[mt][nt][3] + bb.y);
        }
    }
}

// ---------------------------------------------------------------------------
// FP16 flash attention — round-14 version VERBATIM (smem P + ldmatrix; the
// P-in-registers variant regressed). smem = 55296 B.
// ---------------------------------------------------------------------------
#define AKP 36
#define AK_ST (64 * AKP)
#define AV_ST (64 * AKP)
#define AP_SZ (128 * AKP)
#define ATTN_SMEM ((2 * AK_ST + 2 * AV_ST + AP_SZ) * 4)

__global__ __launch_bounds__(256)
void attn_f16(const uint32_t* __restrict__ Q,
              const uint32_t* __restrict__ K,
              const uint32_t* __restrict__ V,
              uint32_t* __restrict__ O)
{
    extern __shared__ uint32_t sa[];
    uint32_t* Kbuf = sa;
    uint32_t* Vbuf = sa + 2 * AK_ST;
    uint32_t* Ps   = sa + 2 * AK_ST + 2 * AV_ST;

    const int tid  = threadIdx.x;
    const int lane = tid & 31;
    const int wid  = tid >> 5;
    const int gid  = lane >> 2;
    const int tg   = lane & 3;
    const int rb   = wid * 16;

    const int q0 = blockIdx.x * 128;
    const int h  = blockIdx.y;
    const int b  = blockIdx.z;

    const int aoff = ldsm_a_off(lane, AKP);
    const int boff = ldsm_b_off(lane, AKP);

    const uint32_t* Qb  = Q + (size_t)b * SEQ * 512 + h * 32;
    const uint32_t* Kb  = K + (size_t)b * SEQ * 512 + h * 32;
    const uint32_t* Vtb = V + ((size_t)(b * 16 + h) * 64) * 1024;

    uint32_t qf[4][4];
    {
        const uint32_t* qr0 = Qb + (size_t)(q0 + rb + gid) * 512;
        const uint32_t* qr1 = qr0 + (size_t)8 * 512;
        #pragma unroll
        for (int ks = 0; ks < 4; ks++) {
            qf[ks][0] = qr0[ks * 8 + tg    ];
            qf[ks][1] = qr1[ks * 8 + tg    ];
            qf[ks][2] = qr0[ks * 8 + tg + 4];
            qf[ks][3] = qr1[ks * 8 + tg + 4];
        }
    }

    #pragma unroll
    for (int i = 0; i < 2; i++) {
        int idx = tid + i * 256;
        int r = idx >> 3, ch = (idx & 7) * 4;
        cpasync16(smem_u32(&Kbuf[r * AKP + ch]), &Kb[(size_t)r * 512 + ch]);
        cpasync16(smem_u32(&Vbuf[r * AKP + ch]), &Vtb[(size_t)r * 1024 + ch]);
    }
    cpasync_commit();

    float o[8][4];
    #pragma unroll
    for (int nt = 0; nt < 8; nt++)
        #pragma unroll
        for (int i = 0; i < 4; i++) o[nt][i] = 0.f;
    float m_i[2] = { -1e30f, -1e30f };
    float l_i[2] = { 0.f, 0.f };

    int st = 0;
    for (int kt = 0; kt < SEQ; kt += 64) {
        cpasync_wait<0>();
        __syncthreads();

        if (kt + 64 < SEQ) {
            uint32_t* Kd = Kbuf + (st ^ 1) * AK_ST;
            uint32_t* Vd = Vbuf + (st ^ 1) * AV_ST;
            #pragma unroll
            for (int i = 0; i < 2; i++) {
                int idx = tid + i * 256;
                int r = idx >> 3, ch = (idx & 7) * 4;
                cpasync16(smem_u32(&Kd[r * AKP + ch]),
                          &Kb[(size_t)(kt + 64 + r) * 512 + ch]);
                cpasync16(smem_u32(&Vd[r * AKP + ch]),
                          &Vtb[(size_t)r * 1024 + (kt + 64) / 2 + ch]);
            }
            cpasync_commit();
        }

        const uint32_t* Ks = Kbuf + st * AK_ST;
        const uint32_t* Vs = Vbuf + st * AV_ST;

        float s[8][4];
        #pragma unroll
        for (int nt = 0; nt < 8; nt++)
            #pragma unroll
            for (int i = 0; i < 4; i++) s[nt][i] = 0.f;

        #pragma unroll
        for (int ks = 0; ks < 4; ks++) {
            uint32_t kf[8][2];
            #pragma unroll
            for (int ntp = 0; ntp < 4; ntp++) {
                int base = (ntp * 16) * AKP + ks * 8 + boff;
                ldsm_x4(kf[ntp * 2][0], kf[ntp * 2][1],
                        kf[ntp * 2 + 1][0], kf[ntp * 2 + 1][1],
                        smem_u32(&Ks[base]));
            }
            #pragma unroll
            for (int nt = 0; nt < 8; nt++)
                mma_f16(s[nt], qf[ks][0], qf[ks][1], qf[ks][2], qf[ks][3],
                        kf[nt][0], kf[nt][1]);
        }

        #pragma unroll
        for (int half = 0; half < 2; half++) {
            float mx = -1e30f;
            #pragma unroll
            for (int nt = 0; nt < 8; nt++)
                mx = fmaxf(mx, fmaxf(s[nt][half * 2], s[nt][half * 2 + 1]));
            mx = fmaxf(mx, __shfl_xor_sync(0xffffffffu, mx, 1));
            mx = fmaxf(mx, __shfl_xor_sync(0xffffffffu, mx, 2));

            float mnew = fmaxf(m_i[half], mx);
            float corr = __expf(m_i[half] - mnew);
            float rs = 0.f;
            #pragma unroll
            for (int nt = 0; nt < 8; nt++) {
                s[nt][half * 2]     = __expf(s[nt][half * 2]     - mnew);
                s[nt][half * 2 + 1] = __expf(s[nt][half * 2 + 1] - mnew);
                rs += s[nt][half * 2] + s[nt][half * 2 + 1];
            }
            rs += __shfl_xor_sync(0xffffffffu, rs, 1);
            rs += __shfl_xor_sync(0xffffffffu, rs, 2);

            l_i[half] = l_i[half] * corr + rs;
            m_i[half] = mnew;
            #pragma unroll
            for (int nt = 0; nt < 8; nt++) {
                o[nt][half * 2]     *= corr;
                o[nt][half * 2 + 1] *= corr;
            }
        }

        __syncwarp();
        #pragma unroll
        for (int nt = 0; nt < 8; nt++) {
            Ps[(rb + gid    ) * AKP + nt * 4 + tg] = pack_h2(s[nt][0], s[nt][1]);
            Ps[(rb + gid + 8) * AKP + nt * 4 + tg] = pack_h2(s[nt][2], s[nt][3]);
        }
        __syncwarp();

        #pragma unroll
        for (int ks = 0; ks < 4; ks++) {
            uint32_t pf[4];
            ldsm_x4(pf[0], pf[1], pf[2], pf[3],
                    smem_u32(&Ps[rb * AKP + ks * 8 + aoff]));
            uint32_t vf[8][2];
            #pragma unroll
            for (int ntp = 0; ntp < 4; ntp++) {
                int base = (ntp * 16) * AKP + ks * 8 + boff;
                ldsm_x4(vf[ntp * 2][0], vf[ntp * 2][1],
                        vf[ntp * 2 + 1][0], vf[ntp * 2 + 1][1],
                        smem_u32(&Vs[base]));
            }
            #pragma unroll
            for (int nt = 0; nt < 8; nt++)
                mma_f16(o[nt], pf[0], pf[1], pf[2], pf[3], vf[nt][0], vf[nt][1]);
        }
        st ^= 1;
    }

    float inv0 = 1.0f / l_i[0];
    float inv1 = 1.0f / l_i[1];
    uint32_t* Ob = O + (size_t)b * SEQ * 512 + h * 32;
    int r0 = q0 + rb + gid;
    #pragma unroll
    for (int nt = 0; nt < 8; nt++) {
        int u = nt * 4 + tg;
        Ob[(size_t)r0 * 512 + u]       = pack_h2(o[nt][0] * inv0, o[nt][1] * inv0);
        Ob[(size_t)(r0 + 8) * 512 + u] = pack_h2(o[nt][2] * inv1, o[nt][3] * inv1);
    }
}

// ---------------------------------------------------------------------------
// kernel_launch — inputs: q, k, v, w_q, b_q, w_k, b_k, w_v, b_v, w_o, b_o
// ---------------------------------------------------------------------------
extern "C" void kernel_launch(void* const* d_in, const int* in_sizes, int n_in,
                              void* d_out, int out_size)
{
    const float* q   = (const float*)d_in[0];
    const float* k   = (const float*)d_in[1];
    const float* v   = (const float*)d_in[2];
    const float* w_q = (const float*)d_in[3];
    const float* b_q = (const float*)d_in[4];
    const float* w_k = (const float*)d_in[5];
    const float* b_k = (const float*)d_in[6];
    const float* w_v = (const float*)d_in[7];
    const float* b_v = (const float*)d_in[8];
    const float* w_o = (const float*)d_in[9];
    const float* b_o = (const float*)d_in[10];
    float* out = (float*)d_out;

    uint32_t *tq, *tk, *tv, *twq, *twk, *twv, *two, *gq, *gk, *gv, *go;
    cudaGetSymbolAddress((void**)&tq,  t_q);
    cudaGetSymbolAddress((void**)&tk,  t_k);
    cudaGetSymbolAddress((void**)&tv,  t_v);
    cudaGetSymbolAddress((void**)&twq, t_wq);
    cudaGetSymbolAddress((void**)&twk, t_wk);
    cudaGetSymbolAddress((void**)&twv, t_wv);
    cudaGetSymbolAddress((void**)&two, t_wo);
    cudaGetSymbolAddress((void**)&gq,  g_Q);
    cudaGetSymbolAddress((void**)&gk,  g_K);
    cudaGetSymbolAddress((void**)&gv,  g_V);
    cudaGetSymbolAddress((void**)&go,  g_O);

    cudaFuncSetAttribute(gemm_qkv, cudaFuncAttributeMaxDynamicSharedMemorySize, GEMM_SMEM);
    cudaFuncSetAttribute(gemm_out, cudaFuncAttributeMaxDynamicSharedMemorySize, GEMM_SMEM);
    cudaFuncSetAttribute(attn_f16, cudaFuncAttributeMaxDynamicSharedMemorySize, ATTN_SMEM);

    const int n4_act = M_ROWS * D_MODEL / 4;          // 1048576
    dim3 prep_grid(n4_act / 256, 1, 7);               // (4096, 1, 7)
    prep_kernel<<<prep_grid, 256>>>((const float4*)q, (const float4*)k, (const float4*)v,
                                    (uint2*)tq, (uint2*)tk, (uint2*)tv,
                                    w_q, w_k, w_v, w_o,
                                    (__half*)twq, (__half*)twk, (__half*)twv, (__half*)two,
                                    n4_act);

    dim3 qkv_grid(D_MODEL / 128, M_ROWS / 128, 3);    // (8, 32, 3) = 768 CTAs
    gemm_qkv<<<qkv_grid, 256, GEMM_SMEM>>>(b_q, b_k, b_v);

    dim3 attn_grid(SEQ / 128, N_HEADS, BATCH);        // (16, 16, 2)
    attn_f16<<<attn_grid, 256, ATTN_SMEM>>>(gq, gk, gv, go);

    dim3 out_grid(D_MODEL / 128, M_ROWS / 128);       // (8, 32)
    gemm_out<<<out_grid, 256, GEMM_SMEM>>>(b_o, out);
}